// round 4
// baseline (speedup 1.0000x reference)
#include <cuda_runtime.h>

// ---------------------------------------------------------------------------
// GIN layer:  agg = segment_max(feats[src], dst) (empty -> 0)
//             h   = feats + agg
//             h1  = relu(BN(h @ W1 + b1))
//             h2  = relu(BN(h1 @ W2 + b2))
//             out = BN(h2)
// BN = training-mode batch norm over the node axis (biased variance).
//
// R2 structure: BN stats fused into GEMM epilogue; no overflow buffer
// (deterministic rescan fallback); cnt re-zeroed by final kernel.
// ---------------------------------------------------------------------------

#define N_NODES 50000
#define N_EDGES 800000
#define D 128
#define CAP 128               // per-node edge bucket capacity (mean deg = 16)
#define BN_EPS 1e-5f
#define NBLK_GEMM 391         // ceil(50000 / 128)
#define NBLK_RED 500          // colreduce3 blocks (100 rows each)

// ----------------------------- scratch (static, no allocs) -----------------
__device__ int   d_cnt[N_NODES];                 // zero-init at load; re-zeroed each run
__device__ int   d_bucket[N_NODES * CAP];
__device__ float d_H [N_NODES * D];              // feats + agg
__device__ float d_Y1[N_NODES * D];              // H @ W1 + b1
__device__ float d_Y2[N_NODES * D];              // h1 @ W2 + b2
__device__ float d_psum[NBLK_RED * D];
__device__ float d_psq [NBLK_RED * D];
__device__ float d_scale1[D], d_shift1[D];
__device__ float d_scale2[D], d_shift2[D];
__device__ float d_scale3[D], d_shift3[D];

// ----------------------------- K1: scatter edges into dst buckets ----------
__global__ void scatter_kernel(const int* __restrict__ src,
                               const int* __restrict__ dst) {
    int e = blockIdx.x * blockDim.x + threadIdx.x;
    if (e >= N_EDGES) return;
    int dn = dst[e], sn = src[e];
    int p = atomicAdd(&d_cnt[dn], 1);
    if (p < CAP) d_bucket[dn * CAP + p] = sn;
    // overflow: nothing stored; aggregate_kernel rescans all edges for
    // that node (deterministic; essentially never taken at mean degree 16)
}

// ----------------------------- K2: warp-per-node max aggregation -----------
__global__ void aggregate_kernel(const float* __restrict__ feats,
                                 const int* __restrict__ src,
                                 const int* __restrict__ dst) {
    int gtid = blockIdx.x * blockDim.x + threadIdx.x;
    int node = gtid >> 5;
    int lane = gtid & 31;
    if (node >= N_NODES) return;
    const float4* f4 = reinterpret_cast<const float4*>(feats);

    int c = d_cnt[node];
    float4 acc = make_float4(-3.402823466e38f, -3.402823466e38f,
                             -3.402823466e38f, -3.402823466e38f);
    if (c <= CAP) {
        const int* bk = d_bucket + node * CAP;
        int e = 0;
        for (; e + 4 <= c; e += 4) {             // 4-way MLP on the gather
            int s0 = bk[e+0], s1 = bk[e+1], s2 = bk[e+2], s3 = bk[e+3];
            float4 v0 = f4[s0 * 32 + lane];
            float4 v1 = f4[s1 * 32 + lane];
            float4 v2 = f4[s2 * 32 + lane];
            float4 v3 = f4[s3 * 32 + lane];
            acc.x = fmaxf(acc.x, fmaxf(fmaxf(v0.x, v1.x), fmaxf(v2.x, v3.x)));
            acc.y = fmaxf(acc.y, fmaxf(fmaxf(v0.y, v1.y), fmaxf(v2.y, v3.y)));
            acc.z = fmaxf(acc.z, fmaxf(fmaxf(v0.z, v1.z), fmaxf(v2.z, v3.z)));
            acc.w = fmaxf(acc.w, fmaxf(fmaxf(v0.w, v1.w), fmaxf(v2.w, v3.w)));
        }
        for (; e < c; ++e) {
            int s = bk[e];
            float4 v = f4[s * 32 + lane];
            acc.x = fmaxf(acc.x, v.x); acc.y = fmaxf(acc.y, v.y);
            acc.z = fmaxf(acc.z, v.z); acc.w = fmaxf(acc.w, v.w);
        }
    } else {
        // never-path: bucket overflow -> full deterministic rescan
        for (int e = 0; e < N_EDGES; ++e) {
            if (dst[e] == node) {
                float4 v = f4[src[e] * 32 + lane];
                acc.x = fmaxf(acc.x, v.x); acc.y = fmaxf(acc.y, v.y);
                acc.z = fmaxf(acc.z, v.z); acc.w = fmaxf(acc.w, v.w);
            }
        }
    }
    float4 b = f4[node * 32 + lane];
    float4 h;
    if (c == 0) h = b;                           // empty segment -> agg = 0
    else { h.x = b.x + acc.x; h.y = b.y + acc.y;
           h.z = b.z + acc.z; h.w = b.w + acc.w; }
    reinterpret_cast<float4*>(d_H)[node * 32 + lane] = h;
}

// ----------------------------- fp32 SGEMM + fused BN column stats ----------
// Block: 256 thr, tile 128(M) x 128(N) x 128(full K).  A-load transform:
// identity, or relu(ts[k]*x + tt[k]) (folds previous BN+ReLU).
// Epilogue writes Y = f(A)@W + bias and per-block column sum/sumsq partials.
__global__ void __launch_bounds__(256)
gemm_kernel(const float* __restrict__ A, const float* __restrict__ Wg,
            const float* __restrict__ bias, float* __restrict__ Y,
            const float* __restrict__ ts, const float* __restrict__ tt) {
    extern __shared__ float smem[];
    float* As = smem;             // [128][128] row-major (m, k)
    float* Ws = smem + 128 * 128; // [128][128] row-major (k, n)

    const int tcol = threadIdx.x & 15;
    const int trow = threadIdx.x >> 4;
    const int block_row = blockIdx.x * 128;

    const float4* A4 = reinterpret_cast<const float4*>(A);
    const float4* W4 = reinterpret_cast<const float4*>(Wg);
    float4*       As4 = reinterpret_cast<float4*>(As);
    float4*       Ws4 = reinterpret_cast<float4*>(Ws);

    #pragma unroll
    for (int i = 0; i < 16; ++i) {
        int f4i = threadIdx.x + i * 256;      // 0..4095
        int m   = f4i >> 5;
        int k4  = f4i & 31;
        int row = block_row + m;
        float4 v = make_float4(0.f, 0.f, 0.f, 0.f);
        if (row < N_NODES) v = A4[row * 32 + k4];
        if (ts) {
            int k = k4 * 4;
            v.x = fmaxf(fmaf(ts[k+0], v.x, tt[k+0]), 0.f);
            v.y = fmaxf(fmaf(ts[k+1], v.y, tt[k+1]), 0.f);
            v.z = fmaxf(fmaf(ts[k+2], v.z, tt[k+2]), 0.f);
            v.w = fmaxf(fmaf(ts[k+3], v.w, tt[k+3]), 0.f);
        }
        As4[f4i] = v;
        Ws4[f4i] = W4[f4i];
    }
    __syncthreads();

    float acc[8][8];
    #pragma unroll
    for (int i = 0; i < 8; ++i)
        #pragma unroll
        for (int j = 0; j < 8; ++j) acc[i][j] = 0.f;

    #pragma unroll 4
    for (int k = 0; k < 128; ++k) {
        float a[8], b[8];
        #pragma unroll
        for (int i = 0; i < 8; ++i) a[i] = As[(trow * 8 + i) * 128 + k];
        *(float4*)&b[0] = *(const float4*)&Ws[k * 128 + tcol * 8];
        *(float4*)&b[4] = *(const float4*)&Ws[k * 128 + tcol * 8 + 4];
        #pragma unroll
        for (int i = 0; i < 8; ++i)
            #pragma unroll
            for (int j = 0; j < 8; ++j)
                acc[i][j] = fmaf(a[i], b[j], acc[i][j]);
    }

    float bb[8];
    #pragma unroll
    for (int j = 0; j < 8; ++j) bb[j] = bias[tcol * 8 + j];

    float cs[8], cq[8];
    #pragma unroll
    for (int j = 0; j < 8; ++j) { cs[j] = 0.f; cq[j] = 0.f; }

    #pragma unroll
    for (int i = 0; i < 8; ++i) {
        int row = block_row + trow * 8 + i;
        if (row < N_NODES) {
            float v[8];
            #pragma unroll
            for (int j = 0; j < 8; ++j) {
                v[j] = acc[i][j] + bb[j];
                cs[j] += v[j];
                cq[j] += v[j] * v[j];
            }
            float4* Yr = reinterpret_cast<float4*>(Y + row * 128 + tcol * 8);
            Yr[0] = make_float4(v[0], v[1], v[2], v[3]);
            Yr[1] = make_float4(v[4], v[5], v[6], v[7]);
        }
    }

    // deterministic per-block column-stat reduction (reuse smem)
    __syncthreads();
    float* ssum = smem;            // [16][128]
    float* ssq  = smem + 2048;     // [16][128]
    #pragma unroll
    for (int j = 0; j < 8; ++j) {
        ssum[trow * 128 + tcol * 8 + j] = cs[j];
        ssq [trow * 128 + tcol * 8 + j] = cq[j];
    }
    __syncthreads();
    if (threadIdx.x < 128) {
        float s = 0.f, q = 0.f;
        #pragma unroll
        for (int t = 0; t < 16; ++t) {
            s += ssum[t * 128 + threadIdx.x];
            q += ssq [t * 128 + threadIdx.x];
        }
        d_psum[blockIdx.x * 128 + threadIdx.x] = s;
        d_psq [blockIdx.x * 128 + threadIdx.x] = q;
    }
}

// ----------------------------- colreduce (phase-3 stats only) --------------
// sum & sumsq per column of relu(ts*X + tt)
__global__ void colreduce_kernel(const float* __restrict__ X,
                                 const float* __restrict__ ts,
                                 const float* __restrict__ tt) {
    int c = threadIdx.x;                          // 128 threads = 128 columns
    int r0 = blockIdx.x * 100;
    int r1 = r0 + 100; if (r1 > N_NODES) r1 = N_NODES;
    float sc = ts[c];
    float sh = tt[c];
    float sm = 0.f, sq = 0.f;
    for (int r = r0; r < r1; ++r) {
        float v = fmaxf(fmaf(sc, X[r * 128 + c], sh), 0.f);
        sm += v; sq += v * v;
    }
    d_psum[blockIdx.x * 128 + c] = sm;
    d_psq [blockIdx.x * 128 + c] = sq;
}

__global__ void finalize_kernel(const float* __restrict__ g,
                                const float* __restrict__ be,
                                float* __restrict__ scale,
                                float* __restrict__ shift,
                                int nblk) {
    int c = threadIdx.x;
    float sm = 0.f, sq = 0.f;
    for (int b = 0; b < nblk; ++b) {              // fixed order -> deterministic
        sm += d_psum[b * 128 + c];
        sq += d_psq [b * 128 + c];
    }
    float m = sm / (float)N_NODES;
    float v = sq / (float)N_NODES - m * m;
    float a = g[c] * rsqrtf(v + BN_EPS);
    scale[c] = a;
    shift[c] = be[c] - m * a;
}

// ----------------------------- final elementwise ---------------------------
// out = s3 * relu(s2*Y2 + t2) + t3 ; also re-zeros d_cnt for the next replay
__global__ void final_kernel(float* __restrict__ out) {
    int i = blockIdx.x * blockDim.x + threadIdx.x;
    if (i >= N_NODES * D) return;
    if (i < N_NODES) d_cnt[i] = 0;               // prep next graph replay
    int c = i & 127;
    float v = d_Y2[i];
    float h = fmaxf(fmaf(d_scale2[c], v, d_shift2[c]), 0.f);
    out[i] = fmaf(d_scale3[c], h, d_shift3[c]);
}

// ---------------------------------------------------------------------------
extern "C" void kernel_launch(void* const* d_in, const int* in_sizes, int n_in,
                              void* d_out, int out_size) {
    const float* feats = (const float*)d_in[0];
    const int*   src   = (const int*)  d_in[1];
    const int*   dst   = (const int*)  d_in[2];
    const float* W1    = (const float*)d_in[3];
    const float* b1    = (const float*)d_in[4];
    const float* g1    = (const float*)d_in[5];
    const float* be1   = (const float*)d_in[6];
    const float* W2    = (const float*)d_in[7];
    const float* b2    = (const float*)d_in[8];
    const float* g2    = (const float*)d_in[9];
    const float* be2   = (const float*)d_in[10];
    const float* g3    = (const float*)d_in[11];
    const float* be3   = (const float*)d_in[12];
    float* out = (float*)d_out;

    static bool attr_set = false;
    const int GEMM_SMEM = 2 * 128 * 128 * sizeof(float);  // 128 KB
    if (!attr_set) {
        cudaFuncSetAttribute(gemm_kernel,
                             cudaFuncAttributeMaxDynamicSharedMemorySize,
                             GEMM_SMEM);
        attr_set = true;
    }

    float *s1, *t1, *s2, *t2, *s3, *t3;
    cudaGetSymbolAddress((void**)&s1, d_scale1);
    cudaGetSymbolAddress((void**)&t1, d_shift1);
    cudaGetSymbolAddress((void**)&s2, d_scale2);
    cudaGetSymbolAddress((void**)&t2, d_shift2);
    cudaGetSymbolAddress((void**)&s3, d_scale3);
    cudaGetSymbolAddress((void**)&t3, d_shift3);
    float *H, *Y1, *Y2;
    cudaGetSymbolAddress((void**)&H,  d_H);
    cudaGetSymbolAddress((void**)&Y1, d_Y1);
    cudaGetSymbolAddress((void**)&Y2, d_Y2);

    const int ND = N_NODES * D;

    scatter_kernel<<<(N_EDGES + 255) / 256, 256>>>(src, dst);
    aggregate_kernel<<<(N_NODES * 32 + 255) / 256, 256>>>(feats, src, dst);

    // Y1 = H @ W1 + b1   (+ fused column stats)
    gemm_kernel<<<NBLK_GEMM, 256, GEMM_SMEM>>>(H, W1, b1, Y1, nullptr, nullptr);
    finalize_kernel<<<1, 128>>>(g1, be1, s1, t1, NBLK_GEMM);
    // Y2 = relu(BN(Y1)) @ W2 + b2   (BN+ReLU fused into A load, stats fused)
    gemm_kernel<<<NBLK_GEMM, 256, GEMM_SMEM>>>(Y1, W2, b2, Y2, s1, t1);
    finalize_kernel<<<1, 128>>>(g2, be2, s2, t2, NBLK_GEMM);
    // stats of h2 = relu(BN(Y2))
    colreduce_kernel<<<NBLK_RED, 128>>>(Y2, s2, t2);
    finalize_kernel<<<1, 128>>>(g3, be3, s3, t3, NBLK_RED);
    // out = BN3(relu(BN2(Y2)))  (+ re-zero d_cnt)
    final_kernel<<<(ND + 255) / 256, 256>>>(out);
}

// round 7
// speedup vs baseline: 1.1564x; 1.1564x over previous
#include <cuda_runtime.h>

// ---------------------------------------------------------------------------
// GIN layer:  agg = segment_max(feats[src], dst) (empty -> 0)
//             h   = feats + agg
//             h1  = relu(BN(h @ W1 + b1))
//             h2  = relu(BN(h1 @ W2 + b2))
//             out = BN(h2)
// R5: parallel finalize (was 38.5us serial!), 512-thread GEMM.
// ---------------------------------------------------------------------------

#define N_NODES 50000
#define N_EDGES 800000
#define D 128
#define CAP 128               // per-node edge bucket capacity (mean deg = 16)
#define BN_EPS 1e-5f
#define NBLK_GEMM 391         // ceil(50000 / 128)
#define NBLK_RED 500          // colreduce3 blocks (100 rows each)

// ----------------------------- scratch (static, no allocs) -----------------
__device__ int   d_cnt[N_NODES];                 // zero-init; re-zeroed each run
__device__ int   d_bucket[N_NODES * CAP];
__device__ float d_H [N_NODES * D];
__device__ float d_Y1[N_NODES * D];
__device__ float d_Y2[N_NODES * D];
__device__ float d_psum[NBLK_RED * D];
__device__ float d_psq [NBLK_RED * D];
__device__ float d_scale1[D], d_shift1[D];
__device__ float d_scale2[D], d_shift2[D];
__device__ float d_scale3[D], d_shift3[D];

// ----------------------------- K1: scatter edges into dst buckets ----------
__global__ void scatter_kernel(const int* __restrict__ src,
                               const int* __restrict__ dst) {
    int e = blockIdx.x * blockDim.x + threadIdx.x;
    if (e >= N_EDGES) return;
    int dn = dst[e], sn = src[e];
    int p = atomicAdd(&d_cnt[dn], 1);
    if (p < CAP) d_bucket[dn * CAP + p] = sn;
    // overflow: aggregate_kernel rescans all edges for that node
}

// ----------------------------- K2: warp-per-node max aggregation -----------
__global__ void aggregate_kernel(const float* __restrict__ feats,
                                 const int* __restrict__ src,
                                 const int* __restrict__ dst) {
    int gtid = blockIdx.x * blockDim.x + threadIdx.x;
    int node = gtid >> 5;
    int lane = gtid & 31;
    if (node >= N_NODES) return;
    const float4* f4 = reinterpret_cast<const float4*>(feats);

    int c = d_cnt[node];
    float4 acc = make_float4(-3.402823466e38f, -3.402823466e38f,
                             -3.402823466e38f, -3.402823466e38f);
    if (c <= CAP) {
        const int* bk = d_bucket + node * CAP;
        int e = 0;
        for (; e + 4 <= c; e += 4) {
            int s0 = bk[e+0], s1 = bk[e+1], s2 = bk[e+2], s3 = bk[e+3];
            float4 v0 = f4[s0 * 32 + lane];
            float4 v1 = f4[s1 * 32 + lane];
            float4 v2 = f4[s2 * 32 + lane];
            float4 v3 = f4[s3 * 32 + lane];
            acc.x = fmaxf(acc.x, fmaxf(fmaxf(v0.x, v1.x), fmaxf(v2.x, v3.x)));
            acc.y = fmaxf(acc.y, fmaxf(fmaxf(v0.y, v1.y), fmaxf(v2.y, v3.y)));
            acc.z = fmaxf(acc.z, fmaxf(fmaxf(v0.z, v1.z), fmaxf(v2.z, v3.z)));
            acc.w = fmaxf(acc.w, fmaxf(fmaxf(v0.w, v1.w), fmaxf(v2.w, v3.w)));
        }
        for (; e < c; ++e) {
            int s = bk[e];
            float4 v = f4[s * 32 + lane];
            acc.x = fmaxf(acc.x, v.x); acc.y = fmaxf(acc.y, v.y);
            acc.z = fmaxf(acc.z, v.z); acc.w = fmaxf(acc.w, v.w);
        }
    } else {
        for (int e = 0; e < N_EDGES; ++e) {      // never-path, deterministic
            if (dst[e] == node) {
                float4 v = f4[src[e] * 32 + lane];
                acc.x = fmaxf(acc.x, v.x); acc.y = fmaxf(acc.y, v.y);
                acc.z = fmaxf(acc.z, v.z); acc.w = fmaxf(acc.w, v.w);
            }
        }
    }
    float4 b = f4[node * 32 + lane];
    float4 h;
    if (c == 0) h = b;
    else { h.x = b.x + acc.x; h.y = b.y + acc.y;
           h.z = b.z + acc.z; h.w = b.w + acc.w; }
    reinterpret_cast<float4*>(d_H)[node * 32 + lane] = h;
}

// ----------------------------- fp32 SGEMM + fused BN column stats ----------
// 512 threads, tile 128(M) x 128(N) x 128(full K), 8x4 microtile.
__global__ void __launch_bounds__(512)
gemm_kernel(const float* __restrict__ A, const float* __restrict__ Wg,
            const float* __restrict__ bias, float* __restrict__ Y,
            const float* __restrict__ ts, const float* __restrict__ tt) {
    extern __shared__ float smem[];
    float* As = smem;             // [128][128] (m, k)
    float* Ws = smem + 128 * 128; // [128][128] (k, n)

    const int tid  = threadIdx.x;
    const int tcol = tid & 31;    // cols tcol*4 .. +3
    const int trow = tid >> 5;    // rows trow*8 .. +7  (0..15)
    const int block_row = blockIdx.x * 128;

    const float4* A4 = reinterpret_cast<const float4*>(A);
    const float4* W4 = reinterpret_cast<const float4*>(Wg);
    float4*       As4 = reinterpret_cast<float4*>(As);
    float4*       Ws4 = reinterpret_cast<float4*>(Ws);

    #pragma unroll
    for (int i = 0; i < 8; ++i) {
        int f4i = tid + i * 512;              // 0..4095
        int m   = f4i >> 5;
        int k4  = f4i & 31;
        int row = block_row + m;
        float4 v = make_float4(0.f, 0.f, 0.f, 0.f);
        if (row < N_NODES) v = A4[row * 32 + k4];
        if (ts) {
            int k = k4 * 4;
            v.x = fmaxf(fmaf(ts[k+0], v.x, tt[k+0]), 0.f);
            v.y = fmaxf(fmaf(ts[k+1], v.y, tt[k+1]), 0.f);
            v.z = fmaxf(fmaf(ts[k+2], v.z, tt[k+2]), 0.f);
            v.w = fmaxf(fmaf(ts[k+3], v.w, tt[k+3]), 0.f);
        }
        As4[f4i] = v;
        Ws4[f4i] = W4[f4i];
    }
    __syncthreads();

    float acc[8][4];
    #pragma unroll
    for (int i = 0; i < 8; ++i)
        #pragma unroll
        for (int j = 0; j < 4; ++j) acc[i][j] = 0.f;

    #pragma unroll 4
    for (int k = 0; k < 128; ++k) {
        float a[8];
        #pragma unroll
        for (int i = 0; i < 8; ++i) a[i] = As[(trow * 8 + i) * 128 + k];
        float4 bv = Ws4[k * 32 + tcol];
        #pragma unroll
        for (int i = 0; i < 8; ++i) {
            acc[i][0] = fmaf(a[i], bv.x, acc[i][0]);
            acc[i][1] = fmaf(a[i], bv.y, acc[i][1]);
            acc[i][2] = fmaf(a[i], bv.z, acc[i][2]);
            acc[i][3] = fmaf(a[i], bv.w, acc[i][3]);
        }
    }

    float bb[4];
    #pragma unroll
    for (int j = 0; j < 4; ++j) bb[j] = bias[tcol * 4 + j];

    float cs[4] = {0.f, 0.f, 0.f, 0.f};
    float cq[4] = {0.f, 0.f, 0.f, 0.f};

    #pragma unroll
    for (int i = 0; i < 8; ++i) {
        int row = block_row + trow * 8 + i;
        if (row < N_NODES) {
            float v[4];
            #pragma unroll
            for (int j = 0; j < 4; ++j) {
                v[j] = acc[i][j] + bb[j];
                cs[j] += v[j];
                cq[j] += v[j] * v[j];
            }
            *reinterpret_cast<float4*>(Y + row * 128 + tcol * 4) =
                make_float4(v[0], v[1], v[2], v[3]);
        }
    }

    // deterministic per-block column-stat reduction (reuse smem)
    __syncthreads();
    float* ssum = smem;            // [16][128]
    float* ssq  = smem + 2048;     // [16][128]
    #pragma unroll
    for (int j = 0; j < 4; ++j) {
        ssum[trow * 128 + tcol * 4 + j] = cs[j];
        ssq [trow * 128 + tcol * 4 + j] = cq[j];
    }
    __syncthreads();
    if (tid < 128) {
        float s = 0.f, q = 0.f;
        #pragma unroll
        for (int t = 0; t < 16; ++t) {
            s += ssum[t * 128 + tid];
            q += ssq [t * 128 + tid];
        }
        d_psum[blockIdx.x * 128 + tid] = s;
        d_psq [blockIdx.x * 128 + tid] = q;
    }
}

// ----------------------------- colreduce (phase-3 stats only) --------------
__global__ void colreduce_kernel(const float* __restrict__ X,
                                 const float* __restrict__ ts,
                                 const float* __restrict__ tt) {
    int c = threadIdx.x;
    int r0 = blockIdx.x * 100;
    int r1 = r0 + 100; if (r1 > N_NODES) r1 = N_NODES;
    float sc = ts[c];
    float sh = tt[c];
    float sm = 0.f, sq = 0.f;
    for (int r = r0; r < r1; ++r) {
        float v = fmaxf(fmaf(sc, X[r * 128 + c], sh), 0.f);
        sm += v; sq += v * v;
    }
    d_psum[blockIdx.x * 128 + c] = sm;
    d_psq [blockIdx.x * 128 + c] = sq;
}

// ----------------------------- parallel finalize ---------------------------
// 1024 threads: 8 strided slices per column (fixed order -> deterministic),
// smem combine. Replaces the 38.5us serial single-block version.
__global__ void __launch_bounds__(1024)
finalize_kernel(const float* __restrict__ g, const float* __restrict__ be,
                float* __restrict__ scale, float* __restrict__ shift,
                int nblk) {
    __shared__ float ss[8][128];
    __shared__ float sq[8][128];
    int c  = threadIdx.x & 127;
    int sl = threadIdx.x >> 7;                    // 0..7
    float sm = 0.f, q = 0.f;
    for (int b = sl; b < nblk; b += 8) {          // fixed per-slice order
        sm += d_psum[b * 128 + c];
        q  += d_psq [b * 128 + c];
    }
    ss[sl][c] = sm;
    sq[sl][c] = q;
    __syncthreads();
    if (sl == 0) {
        float S = 0.f, Q = 0.f;
        #pragma unroll
        for (int t = 0; t < 8; ++t) { S += ss[t][c]; Q += sq[t][c]; }
        float m = S / (float)N_NODES;
        float v = Q / (float)N_NODES - m * m;
        float a = g[c] * rsqrtf(v + BN_EPS);
        scale[c] = a;
        shift[c] = be[c] - m * a;
    }
}

// ----------------------------- final elementwise ---------------------------
__global__ void final_kernel(float* __restrict__ out) {
    int i = blockIdx.x * blockDim.x + threadIdx.x;
    if (i >= N_NODES * D) return;
    if (i < N_NODES) d_cnt[i] = 0;               // prep next graph replay
    int c = i & 127;
    float v = d_Y2[i];
    float h = fmaxf(fmaf(d_scale2[c], v, d_shift2[c]), 0.f);
    out[i] = fmaf(d_scale3[c], h, d_shift3[c]);
}

// ---------------------------------------------------------------------------
extern "C" void kernel_launch(void* const* d_in, const int* in_sizes, int n_in,
                              void* d_out, int out_size) {
    const float* feats = (const float*)d_in[0];
    const int*   src   = (const int*)  d_in[1];
    const int*   dst   = (const int*)  d_in[2];
    const float* W1    = (const float*)d_in[3];
    const float* b1    = (const float*)d_in[4];
    const float* g1    = (const float*)d_in[5];
    const float* be1   = (const float*)d_in[6];
    const float* W2    = (const float*)d_in[7];
    const float* b2    = (const float*)d_in[8];
    const float* g2    = (const float*)d_in[9];
    const float* be2   = (const float*)d_in[10];
    const float* g3    = (const float*)d_in[11];
    const float* be3   = (const float*)d_in[12];
    float* out = (float*)d_out;

    static bool attr_set = false;
    const int GEMM_SMEM = 2 * 128 * 128 * sizeof(float);  // 128 KB
    if (!attr_set) {
        cudaFuncSetAttribute(gemm_kernel,
                             cudaFuncAttributeMaxDynamicSharedMemorySize,
                             GEMM_SMEM);
        attr_set = true;
    }

    float *s1, *t1, *s2, *t2, *s3, *t3;
    cudaGetSymbolAddress((void**)&s1, d_scale1);
    cudaGetSymbolAddress((void**)&t1, d_shift1);
    cudaGetSymbolAddress((void**)&s2, d_scale2);
    cudaGetSymbolAddress((void**)&t2, d_shift2);
    cudaGetSymbolAddress((void**)&s3, d_scale3);
    cudaGetSymbolAddress((void**)&t3, d_shift3);
    float *H, *Y1, *Y2;
    cudaGetSymbolAddress((void**)&H,  d_H);
    cudaGetSymbolAddress((void**)&Y1, d_Y1);
    cudaGetSymbolAddress((void**)&Y2, d_Y2);

    const int ND = N_NODES * D;

    scatter_kernel<<<(N_EDGES + 255) / 256, 256>>>(src, dst);
    aggregate_kernel<<<(N_NODES * 32 + 255) / 256, 256>>>(feats, src, dst);

    // Y1 = H @ W1 + b1   (+ fused column stats)
    gemm_kernel<<<NBLK_GEMM, 512, GEMM_SMEM>>>(H, W1, b1, Y1, nullptr, nullptr);
    finalize_kernel<<<1, 1024>>>(g1, be1, s1, t1, NBLK_GEMM);
    // Y2 = relu(BN(Y1)) @ W2 + b2   (BN+ReLU fused into A load, stats fused)
    gemm_kernel<<<NBLK_GEMM, 512, GEMM_SMEM>>>(Y1, W2, b2, Y2, s1, t1);
    finalize_kernel<<<1, 1024>>>(g2, be2, s2, t2, NBLK_GEMM);
    // stats of h2 = relu(BN(Y2))
    colreduce_kernel<<<NBLK_RED, 128>>>(Y2, s2, t2);
    finalize_kernel<<<1, 1024>>>(g3, be3, s3, t3, NBLK_RED);
    // out = BN3(relu(BN2(Y2)))  (+ re-zero d_cnt)
    final_kernel<<<(ND + 255) / 256, 256>>>(out);
}

// round 9
// speedup vs baseline: 1.3101x; 1.1330x over previous
#include <cuda_runtime.h>

// ---------------------------------------------------------------------------
// GIN layer:  agg = segment_max(feats[src], dst) (empty -> 0)
//             h   = feats + agg
//             h1  = relu(BN(h @ W1 + b1))
//             h2  = relu(BN(h1 @ W2 + b2))
//             out = BN(h2)
// R8: finalize = 128 blocks (one per column) x 256 thr, smem tree reduce.
// ---------------------------------------------------------------------------

#define N_NODES 50000
#define N_EDGES 800000
#define D 128
#define CAP 128               // per-node edge bucket capacity (mean deg = 16)
#define BN_EPS 1e-5f
#define NBLK_GEMM 391         // ceil(50000 / 128)
#define NBLK_RED 500          // colreduce3 blocks (100 rows each)

// ----------------------------- scratch (static, no allocs) -----------------
__device__ int   d_cnt[N_NODES];                 // zero-init; re-zeroed each run
__device__ int   d_bucket[N_NODES * CAP];
__device__ float d_H [N_NODES * D];
__device__ float d_Y1[N_NODES * D];
__device__ float d_Y2[N_NODES * D];
__device__ float d_psum[NBLK_RED * D];
__device__ float d_psq [NBLK_RED * D];
__device__ float d_scale1[D], d_shift1[D];
__device__ float d_scale2[D], d_shift2[D];
__device__ float d_scale3[D], d_shift3[D];

// ----------------------------- K1: scatter edges into dst buckets ----------
__global__ void scatter_kernel(const int* __restrict__ src,
                               const int* __restrict__ dst) {
    int e = blockIdx.x * blockDim.x + threadIdx.x;
    if (e >= N_EDGES) return;
    int dn = dst[e], sn = src[e];
    int p = atomicAdd(&d_cnt[dn], 1);
    if (p < CAP) d_bucket[dn * CAP + p] = sn;
    // overflow: aggregate_kernel rescans all edges for that node
}

// ----------------------------- K2: warp-per-node max aggregation -----------
__global__ void aggregate_kernel(const float* __restrict__ feats,
                                 const int* __restrict__ src,
                                 const int* __restrict__ dst) {
    int gtid = blockIdx.x * blockDim.x + threadIdx.x;
    int node = gtid >> 5;
    int lane = gtid & 31;
    if (node >= N_NODES) return;
    const float4* f4 = reinterpret_cast<const float4*>(feats);

    int c = d_cnt[node];
    float4 acc = make_float4(-3.402823466e38f, -3.402823466e38f,
                             -3.402823466e38f, -3.402823466e38f);
    if (c <= CAP) {
        const int* bk = d_bucket + node * CAP;
        int e = 0;
        for (; e + 4 <= c; e += 4) {
            int s0 = bk[e+0], s1 = bk[e+1], s2 = bk[e+2], s3 = bk[e+3];
            float4 v0 = f4[s0 * 32 + lane];
            float4 v1 = f4[s1 * 32 + lane];
            float4 v2 = f4[s2 * 32 + lane];
            float4 v3 = f4[s3 * 32 + lane];
            acc.x = fmaxf(acc.x, fmaxf(fmaxf(v0.x, v1.x), fmaxf(v2.x, v3.x)));
            acc.y = fmaxf(acc.y, fmaxf(fmaxf(v0.y, v1.y), fmaxf(v2.y, v3.y)));
            acc.z = fmaxf(acc.z, fmaxf(fmaxf(v0.z, v1.z), fmaxf(v2.z, v3.z)));
            acc.w = fmaxf(acc.w, fmaxf(fmaxf(v0.w, v1.w), fmaxf(v2.w, v3.w)));
        }
        for (; e < c; ++e) {
            int s = bk[e];
            float4 v = f4[s * 32 + lane];
            acc.x = fmaxf(acc.x, v.x); acc.y = fmaxf(acc.y, v.y);
            acc.z = fmaxf(acc.z, v.z); acc.w = fmaxf(acc.w, v.w);
        }
    } else {
        for (int e = 0; e < N_EDGES; ++e) {      // never-path, deterministic
            if (dst[e] == node) {
                float4 v = f4[src[e] * 32 + lane];
                acc.x = fmaxf(acc.x, v.x); acc.y = fmaxf(acc.y, v.y);
                acc.z = fmaxf(acc.z, v.z); acc.w = fmaxf(acc.w, v.w);
            }
        }
    }
    float4 b = f4[node * 32 + lane];
    float4 h;
    if (c == 0) h = b;
    else { h.x = b.x + acc.x; h.y = b.y + acc.y;
           h.z = b.z + acc.z; h.w = b.w + acc.w; }
    reinterpret_cast<float4*>(d_H)[node * 32 + lane] = h;
}

// ----------------------------- fp32 SGEMM + fused BN column stats ----------
// 512 threads, tile 128(M) x 128(N) x 128(full K), 8x4 microtile.
__global__ void __launch_bounds__(512)
gemm_kernel(const float* __restrict__ A, const float* __restrict__ Wg,
            const float* __restrict__ bias, float* __restrict__ Y,
            const float* __restrict__ ts, const float* __restrict__ tt) {
    extern __shared__ float smem[];
    float* As = smem;             // [128][128] (m, k)
    float* Ws = smem + 128 * 128; // [128][128] (k, n)

    const int tid  = threadIdx.x;
    const int tcol = tid & 31;    // cols tcol*4 .. +3
    const int trow = tid >> 5;    // rows trow*8 .. +7  (0..15)
    const int block_row = blockIdx.x * 128;

    const float4* A4 = reinterpret_cast<const float4*>(A);
    const float4* W4 = reinterpret_cast<const float4*>(Wg);
    float4*       As4 = reinterpret_cast<float4*>(As);
    float4*       Ws4 = reinterpret_cast<float4*>(Ws);

    #pragma unroll
    for (int i = 0; i < 8; ++i) {
        int f4i = tid + i * 512;              // 0..4095
        int m   = f4i >> 5;
        int k4  = f4i & 31;
        int row = block_row + m;
        float4 v = make_float4(0.f, 0.f, 0.f, 0.f);
        if (row < N_NODES) v = A4[row * 32 + k4];
        if (ts) {
            int k = k4 * 4;
            v.x = fmaxf(fmaf(ts[k+0], v.x, tt[k+0]), 0.f);
            v.y = fmaxf(fmaf(ts[k+1], v.y, tt[k+1]), 0.f);
            v.z = fmaxf(fmaf(ts[k+2], v.z, tt[k+2]), 0.f);
            v.w = fmaxf(fmaf(ts[k+3], v.w, tt[k+3]), 0.f);
        }
        As4[f4i] = v;
        Ws4[f4i] = W4[f4i];
    }
    __syncthreads();

    float acc[8][4];
    #pragma unroll
    for (int i = 0; i < 8; ++i)
        #pragma unroll
        for (int j = 0; j < 4; ++j) acc[i][j] = 0.f;

    #pragma unroll 4
    for (int k = 0; k < 128; ++k) {
        float a[8];
        #pragma unroll
        for (int i = 0; i < 8; ++i) a[i] = As[(trow * 8 + i) * 128 + k];
        float4 bv = Ws4[k * 32 + tcol];
        #pragma unroll
        for (int i = 0; i < 8; ++i) {
            acc[i][0] = fmaf(a[i], bv.x, acc[i][0]);
            acc[i][1] = fmaf(a[i], bv.y, acc[i][1]);
            acc[i][2] = fmaf(a[i], bv.z, acc[i][2]);
            acc[i][3] = fmaf(a[i], bv.w, acc[i][3]);
        }
    }

    float bb[4];
    #pragma unroll
    for (int j = 0; j < 4; ++j) bb[j] = bias[tcol * 4 + j];

    float cs[4] = {0.f, 0.f, 0.f, 0.f};
    float cq[4] = {0.f, 0.f, 0.f, 0.f};

    #pragma unroll
    for (int i = 0; i < 8; ++i) {
        int row = block_row + trow * 8 + i;
        if (row < N_NODES) {
            float v[4];
            #pragma unroll
            for (int j = 0; j < 4; ++j) {
                v[j] = acc[i][j] + bb[j];
                cs[j] += v[j];
                cq[j] += v[j] * v[j];
            }
            *reinterpret_cast<float4*>(Y + row * 128 + tcol * 4) =
                make_float4(v[0], v[1], v[2], v[3]);
        }
    }

    // deterministic per-block column-stat reduction (reuse smem)
    __syncthreads();
    float* ssum = smem;            // [16][128]
    float* ssq  = smem + 2048;     // [16][128]
    #pragma unroll
    for (int j = 0; j < 4; ++j) {
        ssum[trow * 128 + tcol * 4 + j] = cs[j];
        ssq [trow * 128 + tcol * 4 + j] = cq[j];
    }
    __syncthreads();
    if (tid < 128) {
        float s = 0.f, q = 0.f;
        #pragma unroll
        for (int t = 0; t < 16; ++t) {
            s += ssum[t * 128 + tid];
            q += ssq [t * 128 + tid];
        }
        d_psum[blockIdx.x * 128 + tid] = s;
        d_psq [blockIdx.x * 128 + tid] = q;
    }
}

// ----------------------------- colreduce (phase-3 stats only) --------------
__global__ void colreduce_kernel(const float* __restrict__ X,
                                 const float* __restrict__ ts,
                                 const float* __restrict__ tt) {
    int c = threadIdx.x;
    int r0 = blockIdx.x * 100;
    int r1 = r0 + 100; if (r1 > N_NODES) r1 = N_NODES;
    float sc = ts[c];
    float sh = tt[c];
    float sm = 0.f, sq = 0.f;
    for (int r = r0; r < r1; ++r) {
        float v = fmaxf(fmaf(sc, X[r * 128 + c], sh), 0.f);
        sm += v; sq += v * v;
    }
    d_psum[blockIdx.x * 128 + c] = sm;
    d_psq [blockIdx.x * 128 + c] = sq;
}

// ----------------------------- parallel finalize ---------------------------
// One block per column (grid=128), 256 threads: <=2 partials per thread,
// fixed-order smem tree reduce. Deterministic; latency fully parallel.
__global__ void __launch_bounds__(256)
finalize_kernel(const float* __restrict__ g, const float* __restrict__ be,
                float* __restrict__ scale, float* __restrict__ shift,
                int nblk) {
    __shared__ float ss[256];
    __shared__ float sq[256];
    const int c = blockIdx.x;          // column 0..127
    const int t = threadIdx.x;
    float sm = 0.f, q = 0.f;
    for (int b = t; b < nblk; b += 256) {        // fixed order per thread
        sm += d_psum[b * 128 + c];
        q  += d_psq [b * 128 + c];
    }
    ss[t] = sm; sq[t] = q;
    __syncthreads();
    #pragma unroll
    for (int s = 128; s > 0; s >>= 1) {          // fixed tree -> deterministic
        if (t < s) { ss[t] += ss[t + s]; sq[t] += sq[t + s]; }
        __syncthreads();
    }
    if (t == 0) {
        float m = ss[0] / (float)N_NODES;
        float v = sq[0] / (float)N_NODES - m * m;
        float a = g[c] * rsqrtf(v + BN_EPS);
        scale[c] = a;
        shift[c] = be[c] - m * a;
    }
}

// ----------------------------- final elementwise ---------------------------
__global__ void final_kernel(float* __restrict__ out) {
    int i = blockIdx.x * blockDim.x + threadIdx.x;
    if (i >= N_NODES * D) return;
    if (i < N_NODES) d_cnt[i] = 0;               // prep next graph replay
    int c = i & 127;
    float v = d_Y2[i];
    float h = fmaxf(fmaf(d_scale2[c], v, d_shift2[c]), 0.f);
    out[i] = fmaf(d_scale3[c], h, d_shift3[c]);
}

// ---------------------------------------------------------------------------
extern "C" void kernel_launch(void* const* d_in, const int* in_sizes, int n_in,
                              void* d_out, int out_size) {
    const float* feats = (const float*)d_in[0];
    const int*   src   = (const int*)  d_in[1];
    const int*   dst   = (const int*)  d_in[2];
    const float* W1    = (const float*)d_in[3];
    const float* b1    = (const float*)d_in[4];
    const float* g1    = (const float*)d_in[5];
    const float* be1   = (const float*)d_in[6];
    const float* W2    = (const float*)d_in[7];
    const float* b2    = (const float*)d_in[8];
    const float* g2    = (const float*)d_in[9];
    const float* be2   = (const float*)d_in[10];
    const float* g3    = (const float*)d_in[11];
    const float* be3   = (const float*)d_in[12];
    float* out = (float*)d_out;

    static bool attr_set = false;
    const int GEMM_SMEM = 2 * 128 * 128 * sizeof(float);  // 128 KB
    if (!attr_set) {
        cudaFuncSetAttribute(gemm_kernel,
                             cudaFuncAttributeMaxDynamicSharedMemorySize,
                             GEMM_SMEM);
        attr_set = true;
    }

    float *s1, *t1, *s2, *t2, *s3, *t3;
    cudaGetSymbolAddress((void**)&s1, d_scale1);
    cudaGetSymbolAddress((void**)&t1, d_shift1);
    cudaGetSymbolAddress((void**)&s2, d_scale2);
    cudaGetSymbolAddress((void**)&t2, d_shift2);
    cudaGetSymbolAddress((void**)&s3, d_scale3);
    cudaGetSymbolAddress((void**)&t3, d_shift3);
    float *H, *Y1, *Y2;
    cudaGetSymbolAddress((void**)&H,  d_H);
    cudaGetSymbolAddress((void**)&Y1, d_Y1);
    cudaGetSymbolAddress((void**)&Y2, d_Y2);

    const int ND = N_NODES * D;

    scatter_kernel<<<(N_EDGES + 255) / 256, 256>>>(src, dst);
    aggregate_kernel<<<(N_NODES * 32 + 255) / 256, 256>>>(feats, src, dst);

    // Y1 = H @ W1 + b1   (+ fused column stats)
    gemm_kernel<<<NBLK_GEMM, 512, GEMM_SMEM>>>(H, W1, b1, Y1, nullptr, nullptr);
    finalize_kernel<<<D, 256>>>(g1, be1, s1, t1, NBLK_GEMM);
    // Y2 = relu(BN(Y1)) @ W2 + b2   (BN+ReLU fused into A load, stats fused)
    gemm_kernel<<<NBLK_GEMM, 512, GEMM_SMEM>>>(Y1, W2, b2, Y2, s1, t1);
    finalize_kernel<<<D, 256>>>(g2, be2, s2, t2, NBLK_GEMM);
    // stats of h2 = relu(BN(Y2))
    colreduce_kernel<<<NBLK_RED, 128>>>(Y2, s2, t2);
    finalize_kernel<<<D, 256>>>(g3, be3, s3, t3, NBLK_RED);
    // out = BN3(relu(BN2(Y2)))  (+ re-zero d_cnt)
    final_kernel<<<(ND + 255) / 256, 256>>>(out);
}